// round 2
// baseline (speedup 1.0000x reference)
#include <cuda_runtime.h>
#include <math.h>

// ---------------- scratch (device globals; no allocations) ----------------
__device__ float g_P[134217728];   // 512 MiB: pre-pool conv output (max: 512x16x128x128)
__device__ float g_X[33554432];    // 128 MiB: residual / stage state
__device__ float g_O[33554432];    // 128 MiB: resblock temp
__device__ float g_ca[512 * 32];
__device__ float g_sp[512 * 2 * 256];
__device__ float g_feat[512 * 256];
__device__ float g_gi[512 * 384];
__device__ float g_hid[512 * 128];

__device__ __forceinline__ float sigf(float x) { return 1.0f / (1.0f + expf(-x)); }

// ---------------- 3x3 conv, pad=1, optional input-ReLU / residual add ------
// Block: (TILE/2)^2 threads, each computes a 2x2 pixel block for all COUT.
// Shared: input tile with halo + full weight set.
template <int CIN, int COUT, int TILE, bool RELU_IN, bool RESID>
__global__ void conv3x3_kernel(const float* __restrict__ in, const float* __restrict__ w,
                               const float* __restrict__ bias, float* out,
                               const float* resid, int H, int W) {
    extern __shared__ float smem[];
    float* s_in = smem;                                   // CIN*(TILE+2)^2
    float* s_w = smem + CIN * (TILE + 2) * (TILE + 2);    // COUT*CIN*9

    const int IW = TILE + 2;
    const int n = blockIdx.z;
    const int ty0 = blockIdx.y * TILE;
    const int tx0 = blockIdx.x * TILE;
    const int tid = threadIdx.x;
    const int nthr = (TILE / 2) * (TILE / 2);

    for (int i = tid; i < COUT * CIN * 9; i += nthr) s_w[i] = w[i];

    for (int i = tid; i < CIN * IW * IW; i += nthr) {
        int ci = i / (IW * IW);
        int rem = i - ci * IW * IW;
        int iy = rem / IW, ix = rem - iy * IW;
        int gy = ty0 + iy - 1, gx = tx0 + ix - 1;
        float v = 0.0f;
        if (gy >= 0 && gy < H && gx >= 0 && gx < W) {
            v = in[((long)(n * CIN + ci) * H + gy) * W + gx];
            if (RELU_IN) v = fmaxf(v, 0.0f);
        }
        s_in[i] = v;
    }
    __syncthreads();

    const int px = (tid % (TILE / 2)) * 2;
    const int py = (tid / (TILE / 2)) * 2;
    constexpr int CB = 8;   // cout register-block

    for (int co0 = 0; co0 < COUT; co0 += CB) {
        float acc[CB][4];
#pragma unroll
        for (int c = 0; c < CB; c++) {
            float bz = bias[co0 + c];
            acc[c][0] = bz; acc[c][1] = bz; acc[c][2] = bz; acc[c][3] = bz;
        }
        for (int ci = 0; ci < CIN; ci++) {
            float taps[16];
            const float* base = s_in + ci * IW * IW + py * IW + px;
#pragma unroll
            for (int r = 0; r < 4; r++)
#pragma unroll
                for (int cc = 0; cc < 4; cc++) taps[r * 4 + cc] = base[r * IW + cc];
#pragma unroll
            for (int c = 0; c < CB; c++) {
                const float* wp = s_w + ((co0 + c) * CIN + ci) * 9;
#pragma unroll
                for (int ky = 0; ky < 3; ky++)
#pragma unroll
                    for (int kx = 0; kx < 3; kx++) {
                        float wv = wp[ky * 3 + kx];
                        acc[c][0] = fmaf(taps[ky * 4 + kx],           wv, acc[c][0]);
                        acc[c][1] = fmaf(taps[ky * 4 + kx + 1],       wv, acc[c][1]);
                        acc[c][2] = fmaf(taps[(ky + 1) * 4 + kx],     wv, acc[c][2]);
                        acc[c][3] = fmaf(taps[(ky + 1) * 4 + kx + 1], wv, acc[c][3]);
                    }
            }
        }
#pragma unroll
        for (int c = 0; c < CB; c++) {
            int co = co0 + c;
#pragma unroll
            for (int p = 0; p < 4; p++) {
                int oy = ty0 + py + (p >> 1);
                int ox = tx0 + px + (p & 1);
                long idx = ((long)(n * COUT + co) * H + oy) * W + ox;
                float v = acc[c][p];
                if (RESID) v += resid[idx];
                out[idx] = v;
            }
        }
    }
}

// ---------------- maxpool 3x3 stride 2 pad 1 ----------------
__global__ void maxpool_kernel(const float* __restrict__ in, float* __restrict__ out,
                               int C, int H, int W) {
    int H2 = H >> 1, W2 = W >> 1;
    long total = (long)512 * C * H2 * W2;
    long i = (long)blockIdx.x * blockDim.x + threadIdx.x;
    if (i >= total) return;
    int ox = (int)(i % W2); long r = i / W2;
    int oy = (int)(r % H2); r /= H2;
    int c = (int)(r % C);   int n = (int)(r / C);
    const float* base = in + (long)(n * C + c) * H * W;
    float m = -3.4e38f;
    int y0 = oy * 2 - 1, x0 = ox * 2 - 1;
#pragma unroll
    for (int dy = 0; dy < 3; dy++) {
        int y = y0 + dy;
        if (y < 0 || y >= H) continue;
#pragma unroll
        for (int dx = 0; dx < 3; dx++) {
            int x = x0 + dx;
            if (x < 0 || x >= W) continue;
            m = fmaxf(m, base[y * W + x]);
        }
    }
    out[(long)(n * C + c) * H2 * W2 + oy * W2 + ox] = m;
}

__global__ void relu_kernel(float* x, long n) {
    long i = (long)blockIdx.x * blockDim.x + threadIdx.x;
    if (i < n) x[i] = fmaxf(x[i], 0.0f);
}

// ---------------- CBAM channel attention: ca[n][c] ----------------
__global__ void cbam_ca_kernel(const float* __restrict__ x, const float* __restrict__ fc1,
                               const float* __restrict__ fc2, float* __restrict__ ca) {
    int n = blockIdx.x;
    __shared__ float s_mean[32], s_max[32], s_hsum[8];
    int tid = threadIdx.x;            // 256 threads: 8 per channel
    int c = tid >> 3, lane = tid & 7;
    const float* base = x + (long)(n * 32 + c) * 256;
    float sm = 0.0f, mx = -3.4e38f;
    for (int i = lane; i < 256; i += 8) {
        float v = base[i];
        sm += v; mx = fmaxf(mx, v);
    }
#pragma unroll
    for (int off = 4; off; off >>= 1) {
        sm += __shfl_down_sync(0xffffffffu, sm, off, 8);
        mx = fmaxf(mx, __shfl_down_sync(0xffffffffu, mx, off, 8));
    }
    if (lane == 0) { s_mean[c] = sm * (1.0f / 256.0f); s_max[c] = mx; }
    __syncthreads();
    if (tid < 8) {
        float hm = 0.0f, hx = 0.0f;
        for (int k = 0; k < 32; k++) {
            float wv = fc1[tid * 32 + k];
            hm += s_mean[k] * wv;
            hx += s_max[k] * wv;
        }
        s_hsum[tid] = fmaxf(hm, 0.0f) + fmaxf(hx, 0.0f);
    }
    __syncthreads();
    if (tid < 32) {
        float o = 0.0f;
        for (int j = 0; j < 8; j++) o += s_hsum[j] * fc2[tid * 8 + j];
        ca[n * 32 + tid] = sigf(o);
    }
}

// apply channel attention in place; emit spatial mean/max maps
__global__ void cbam_apply_ca_kernel(float* x, const float* __restrict__ ca, float* __restrict__ sp) {
    int n = blockIdx.x, p = threadIdx.x;  // 256 threads = one per pixel
    __shared__ float s_ca[32];
    if (p < 32) s_ca[p] = ca[n * 32 + p];
    __syncthreads();
    float sum = 0.0f, mx = -3.4e38f;
#pragma unroll 4
    for (int c = 0; c < 32; c++) {
        long idx = (long)(n * 32 + c) * 256 + p;
        float v = x[idx] * s_ca[c];
        x[idx] = v;
        sum += v; mx = fmaxf(mx, v);
    }
    sp[(long)n * 512 + p] = sum * (1.0f / 32.0f);
    sp[(long)n * 512 + 256 + p] = mx;
}

// 7x7 spatial attention conv + apply
__global__ void cbam_sa_kernel(float* x, const float* __restrict__ sp, const float* __restrict__ spw) {
    int n = blockIdx.x, p = threadIdx.x;
    int oy = p >> 4, ox = p & 15;
    __shared__ float s_sp[512], s_w[98];
    s_sp[p] = sp[(long)n * 512 + p];
    s_sp[256 + p] = sp[(long)n * 512 + 256 + p];
    if (p < 98) s_w[p] = spw[p];
    __syncthreads();
    float a = 0.0f;
#pragma unroll
    for (int ci = 0; ci < 2; ci++)
        for (int ky = 0; ky < 7; ky++) {
            int y = oy + ky - 3;
            if (y < 0 || y >= 16) continue;
            for (int kx = 0; kx < 7; kx++) {
                int xx = ox + kx - 3;
                if (xx < 0 || xx >= 16) continue;
                a = fmaf(s_sp[ci * 256 + y * 16 + xx], s_w[(ci * 7 + ky) * 7 + kx], a);
            }
        }
    float sa = sigf(a);
#pragma unroll 4
    for (int c = 0; c < 32; c++) {
        long idx = (long)(n * 32 + c) * 256 + p;
        x[idx] *= sa;
    }
}

// ---------------- GEMM: C[M,N] = A[M,K] @ B[N,K]^T + bias, opt relu ------
__global__ void gemm_bt_kernel(const float* __restrict__ A, const float* __restrict__ B,
                               const float* __restrict__ bias, float* __restrict__ C,
                               int M, int N, int K, int relu) {
    __shared__ float sA[32 * 33];
    __shared__ float sB[32 * 33];
    int bm = blockIdx.y * 32, bn = blockIdx.x * 32;
    int tid = threadIdx.x;                  // 256
    int tr = tid >> 4, tc = tid & 15;       // 2x2 outputs each
    float acc00 = 0, acc01 = 0, acc10 = 0, acc11 = 0;
    for (int k0 = 0; k0 < K; k0 += 32) {
        for (int i = tid; i < 32 * 32; i += 256) {
            int r = i >> 5, c = i & 31;
            sA[r * 33 + c] = (bm + r < M) ? A[(long)(bm + r) * K + k0 + c] : 0.0f;
            sB[r * 33 + c] = (bn + r < N) ? B[(long)(bn + r) * K + k0 + c] : 0.0f;
        }
        __syncthreads();
#pragma unroll
        for (int k = 0; k < 32; k++) {
            float a0 = sA[(tr * 2) * 33 + k], a1 = sA[(tr * 2 + 1) * 33 + k];
            float b0 = sB[(tc * 2) * 33 + k], b1 = sB[(tc * 2 + 1) * 33 + k];
            acc00 = fmaf(a0, b0, acc00); acc01 = fmaf(a0, b1, acc01);
            acc10 = fmaf(a1, b0, acc10); acc11 = fmaf(a1, b1, acc11);
        }
        __syncthreads();
    }
    float accs[2][2] = {{acc00, acc01}, {acc10, acc11}};
#pragma unroll
    for (int r = 0; r < 2; r++)
#pragma unroll
        for (int c = 0; c < 2; c++) {
            int m = bm + tr * 2 + r, nn = bn + tc * 2 + c;
            if (m < M && nn < N) {
                float v = accs[r][c] + bias[nn];
                if (relu) v = fmaxf(v, 0.0f);
                C[(long)m * N + nn] = v;
            }
        }
}

// ---------------- GRU scan: one block per env b (8 blocks, 384 threads) ----
__global__ void gru_scan_kernel(const float* __restrict__ gi, const float* __restrict__ done,
                                const float* __restrict__ h0, const float* __restrict__ whh,
                                const float* __restrict__ bhh, float* __restrict__ hidden) {
    extern __shared__ float sm[];
    float* s_whh = sm;                 // transposed: [k*384 + j]
    float* s_gh = sm + 128 * 384;      // 384
    float* s_h = s_gh + 384;           // 128
    float* s_hm = s_h + 128;           // 128
    int b = blockIdx.x, j = threadIdx.x;

    for (int i = j; i < 384 * 128; i += 384) {
        int jj = i >> 7, k = i & 127;
        s_whh[k * 384 + jj] = whh[i];
    }
    if (j < 128) s_h[j] = h0[b * 128 + j];
    __syncthreads();

    float bh = bhh[j];
    for (int t = 0; t < 64; t++) {
        float dt = done[t * 8 + b];
        if (j < 128) s_hm[j] = (1.0f - dt) * s_h[j];
        __syncthreads();
        float acc = bh;
#pragma unroll 8
        for (int k = 0; k < 128; k++) acc = fmaf(s_hm[k], s_whh[k * 384 + j], acc);
        s_gh[j] = acc;
        __syncthreads();
        if (j < 128) {
            const float* gr = gi + (long)(t * 8 + b) * 384;
            float r = sigf(gr[j] + s_gh[j]);
            float z = sigf(gr[128 + j] + s_gh[128 + j]);
            float nn = tanhf(gr[256 + j] + r * s_gh[256 + j]);
            float hn = (1.0f - z) * nn + z * s_hm[j];
            s_h[j] = hn;
            hidden[(long)(t * 8 + b) * 128 + j] = hn;
        }
        __syncthreads();
    }
}

// ---------------- actor/critic heads ----------------
__global__ void heads_kernel(const float* __restrict__ hidden, const float* __restrict__ aw,
                             const float* __restrict__ ab, const float* __restrict__ cw,
                             const float* __restrict__ cb, float* __restrict__ out) {
    int row = blockIdx.x, t = threadIdx.x;
    __shared__ float s_h[128];
    s_h[t] = hidden[(long)row * 128 + t];
    __syncthreads();
    if (t < 4) {
        const float* w = (t < 3) ? (aw + t * 128) : cw;
        float s = (t < 3) ? ab[t] : cb[0];
        for (int k = 0; k < 128; k++) s = fmaf(s_h[k], w[k], s);
        out[row * 4 + t] = s;
    }
}

// ---------------- host-side launch helpers ----------------
template <int CIN, int COUT, int TILE, bool RELU_IN, bool RESID>
static void launch_conv(const float* in, const float* w, const float* b,
                        float* out, const float* resid, int H, int W) {
    int smem = (CIN * (TILE + 2) * (TILE + 2) + COUT * CIN * 9) * 4;
    cudaFuncSetAttribute(conv3x3_kernel<CIN, COUT, TILE, RELU_IN, RESID>,
                         cudaFuncAttributeMaxDynamicSharedMemorySize, smem);
    dim3 g(W / TILE, H / TILE, 512);
    conv3x3_kernel<CIN, COUT, TILE, RELU_IN, RESID>
        <<<g, (TILE / 2) * (TILE / 2), smem>>>(in, w, b, out, resid, H, W);
}

static void launch_pool(const float* in, float* out, int C, int H, int W) {
    long total = (long)512 * C * (H / 2) * (W / 2);
    maxpool_kernel<<<(unsigned)((total + 255) / 256), 256>>>(in, out, C, H, W);
}

extern "C" void kernel_launch(void* const* d_in, const int* in_sizes, int n_in,
                              void* d_out, int out_size) {
    (void)in_sizes; (void)n_in; (void)out_size;
    const float* x        = (const float*)d_in[0];
    const float* done     = (const float*)d_in[1];
    const float* grustate = (const float*)d_in[2];
    const float* s0_cw = (const float*)d_in[3];
    const float* s0_cb = (const float*)d_in[4];
    const float* s0_rw = (const float*)d_in[5];
    const float* s0_rb = (const float*)d_in[6];
    const float* s1_cw = (const float*)d_in[7];
    const float* s1_cb = (const float*)d_in[8];
    const float* s1_rw = (const float*)d_in[9];
    const float* s1_rb = (const float*)d_in[10];
    const float* s2_cw = (const float*)d_in[11];
    const float* s2_cb = (const float*)d_in[12];
    const float* s2_rw = (const float*)d_in[13];
    const float* s2_rb = (const float*)d_in[14];
    const float* cbam_fc1 = (const float*)d_in[15];
    const float* cbam_fc2 = (const float*)d_in[16];
    const float* cbam_spw = (const float*)d_in[17];
    const float* fc_w  = (const float*)d_in[18];
    const float* fc_b  = (const float*)d_in[19];
    const float* gwih  = (const float*)d_in[20];
    const float* gwhh  = (const float*)d_in[21];
    const float* gbih  = (const float*)d_in[22];
    const float* gbhh  = (const float*)d_in[23];
    const float* aw    = (const float*)d_in[24];
    const float* ab    = (const float*)d_in[25];
    const float* cw    = (const float*)d_in[26];
    const float* cb    = (const float*)d_in[27];
    float* out = (float*)d_out;

    float *P, *X, *O, *CA, *SP, *FEAT, *GI, *HID;
    cudaGetSymbolAddress((void**)&P, g_P);
    cudaGetSymbolAddress((void**)&X, g_X);
    cudaGetSymbolAddress((void**)&O, g_O);
    cudaGetSymbolAddress((void**)&CA, g_ca);
    cudaGetSymbolAddress((void**)&SP, g_sp);
    cudaGetSymbolAddress((void**)&FEAT, g_feat);
    cudaGetSymbolAddress((void**)&GI, g_gi);
    cudaGetSymbolAddress((void**)&HID, g_hid);

    // ---- stage 0: 6->16 @128 -> pool 64 -> 2 resblocks (16ch @64) ----
    launch_conv<6, 16, 32, false, false>(x, s0_cw, s0_cb, P, nullptr, 128, 128);
    launch_pool(P, X, 16, 128, 128);
    launch_conv<16, 16, 32, true, false>(X, s0_rw + 0 * 2304, s0_rb + 0, O, nullptr, 64, 64);
    launch_conv<16, 16, 32, true, true >(O, s0_rw + 1 * 2304, s0_rb + 16, X, X, 64, 64);
    launch_conv<16, 16, 32, true, false>(X, s0_rw + 2 * 2304, s0_rb + 32, O, nullptr, 64, 64);
    launch_conv<16, 16, 32, true, true >(O, s0_rw + 3 * 2304, s0_rb + 48, X, X, 64, 64);

    // ---- stage 1: 16->32 @64 -> pool 32 -> 2 resblocks (32ch @32) ----
    launch_conv<16, 32, 32, false, false>(X, s1_cw, s1_cb, P, nullptr, 64, 64);
    launch_pool(P, X, 32, 64, 64);
    launch_conv<32, 32, 32, true, false>(X, s1_rw + 0 * 9216, s1_rb + 0, O, nullptr, 32, 32);
    launch_conv<32, 32, 32, true, true >(O, s1_rw + 1 * 9216, s1_rb + 32, X, X, 32, 32);
    launch_conv<32, 32, 32, true, false>(X, s1_rw + 2 * 9216, s1_rb + 64, O, nullptr, 32, 32);
    launch_conv<32, 32, 32, true, true >(O, s1_rw + 3 * 9216, s1_rb + 96, X, X, 32, 32);

    // ---- stage 2: 32->32 @32 -> pool 16 -> 2 resblocks (32ch @16) ----
    launch_conv<32, 32, 32, false, false>(X, s2_cw, s2_cb, P, nullptr, 32, 32);
    launch_pool(P, X, 32, 32, 32);
    launch_conv<32, 32, 16, true, false>(X, s2_rw + 0 * 9216, s2_rb + 0, O, nullptr, 16, 16);
    launch_conv<32, 32, 16, true, true >(O, s2_rw + 1 * 9216, s2_rb + 32, X, X, 16, 16);
    launch_conv<32, 32, 16, true, false>(X, s2_rw + 2 * 9216, s2_rb + 64, O, nullptr, 16, 16);
    launch_conv<32, 32, 16, true, true >(O, s2_rw + 3 * 9216, s2_rb + 96, X, X, 16, 16);

    // ---- final relu + CBAM ----
    relu_kernel<<<(512 * 32 * 256 + 255) / 256, 256>>>(X, (long)512 * 32 * 256);
    cbam_ca_kernel<<<512, 256>>>(X, cbam_fc1, cbam_fc2, CA);
    cbam_apply_ca_kernel<<<512, 256>>>(X, CA, SP);
    cbam_sa_kernel<<<512, 256>>>(X, SP, cbam_spw);

    // ---- FC 8192->256 (+relu) ----
    gemm_bt_kernel<<<dim3(256 / 32, 512 / 32), 256>>>(X, fc_w, fc_b, FEAT, 512, 256, 8192, 1);

    // ---- GRU: precompute input gates, then sequential scan ----
    gemm_bt_kernel<<<dim3(384 / 32, 512 / 32), 256>>>(FEAT, gwih, gbih, GI, 512, 384, 256, 0);
    {
        int smem = (128 * 384 + 384 + 128 + 128) * 4;
        cudaFuncSetAttribute(gru_scan_kernel, cudaFuncAttributeMaxDynamicSharedMemorySize, smem);
        gru_scan_kernel<<<8, 384, smem>>>(GI, done, grustate, gwhh, gbhh, HID);
    }

    // ---- actor / critic heads -> (512, 4) ----
    heads_kernel<<<512, 128>>>(HID, aw, ab, cw, cb, out);
}

// round 3
// speedup vs baseline: 1.4826x; 1.4826x over previous
#include <cuda_runtime.h>
#include <math.h>

// ---------------- scratch (device globals; no allocations) ----------------
__device__ float g_P[134217728];   // 512 MiB: pre-pool conv output (max 512x128x128x16 NHWC)
__device__ float g_X[33554432];    // 128 MiB: stage state (NHWC)
__device__ float g_O[33554432];    // 128 MiB: resblock temp (NHWC)
__device__ float g_ca[512 * 32];
__device__ float g_sp[512 * 2 * 256];
__device__ float g_feat[512 * 256];
__device__ float g_gi[512 * 384];
__device__ float g_hid[512 * 128];
__device__ float g_fcwT[256 * 8192];  // fc_w permuted to NHWC-k order

__device__ __forceinline__ float sigf(float x) { return 1.0f / (1.0f + expf(-x)); }

__device__ __forceinline__ unsigned tf32u(float x) {
    unsigned r;
    asm("cvt.rna.tf32.f32 %0, %1;" : "=r"(r) : "f"(x));
    return r;
}

__device__ __forceinline__ void mma8(float* c, const unsigned* a, unsigned b0, unsigned b1) {
    asm volatile(
        "mma.sync.aligned.m16n8k8.row.col.f32.tf32.tf32.f32 "
        "{%0,%1,%2,%3},{%4,%5,%6,%7},{%8,%9},{%0,%1,%2,%3};"
        : "+f"(c[0]), "+f"(c[1]), "+f"(c[2]), "+f"(c[3])
        : "r"(a[0]), "r"(a[1]), "r"(a[2]), "r"(a[3]), "r"(b0), "r"(b1));
}

// ---------------- 3x3 conv pad=1 via tf32 tensor-core MMA ------------------
// NHWC activations. Block = 256 thr (8 warps), 16x16 output tile per block.
// Per tap (dy,dx): C[pix, cout] += A[pix shifted, cin] @ W[tap][cin, cout].
// smem A: 18x18 halo tile, row stride RS=CINP+4 (conflict-free fragment loads).
// smem W: [tap][cout][cin], cin stride KP=CINP+4.
template <int CIN, int COUT, bool RELU_IN, bool RESID, bool RELU_OUT, bool NCHW>
__global__ __launch_bounds__(256) void conv_mma_kernel(
    const float* __restrict__ in, const float* __restrict__ w,
    const float* __restrict__ bias, float* __restrict__ out,
    const float* __restrict__ resid, int H, int W) {
    constexpr int CINP = (CIN + 7) / 8 * 8;
    constexpr int RS = CINP + 4;
    constexpr int KP = CINP + 4;
    constexpr int NB = COUT / 8;
    constexpr int A_SZ = 324 * RS;       // 18*18 pixels
    constexpr int W_SZ = 9 * COUT * KP;

    extern __shared__ float sm[];
    float* s_in = sm;
    float* s_w = sm + A_SZ;

    const int tid = threadIdx.x;
    const int n = blockIdx.z;
    const int by = blockIdx.y * 16, bx = blockIdx.x * 16;

    for (int i = tid; i < A_SZ + W_SZ; i += 256) sm[i] = 0.0f;
    __syncthreads();

    // weights: global OIHW -> smem [tap][co][ci], tf32-rounded
    for (int i = tid; i < COUT * CIN * 9; i += 256) {
        int co = i / (CIN * 9);
        int r = i - co * CIN * 9;
        int ci = r / 9;
        int tap = r - ci * 9;
        s_w[(tap * COUT + co) * KP + ci] = __uint_as_float(tf32u(w[i]));
    }
    // input tile with halo
    for (int i = tid; i < 324 * CIN; i += 256) {
        int pix, ci;
        if (NCHW) { ci = i / 324; pix = i - ci * 324; }
        else      { pix = i / CIN; ci = i - pix * CIN; }
        int iy = pix / 18, ix = pix - iy * 18;
        int gy = by + iy - 1, gx = bx + ix - 1;
        if (gy >= 0 && gy < H && gx >= 0 && gx < W) {
            float v = NCHW ? in[((long)(n * CIN + ci) * H + gy) * W + gx]
                           : in[((long)(n * H + gy) * W + gx) * CIN + ci];
            if (RELU_IN) v = fmaxf(v, 0.0f);
            s_in[pix * RS + ci] = __uint_as_float(tf32u(v));
        }
    }
    __syncthreads();

    const int warp = tid >> 5, lane = tid & 31, g = lane >> 2, t = lane & 3;
    const int pyw = warp * 2;   // warp covers tile rows pyw, pyw+1 (16 px each)

    float acc[2][NB][4];
#pragma unroll
    for (int m = 0; m < 2; m++)
#pragma unroll
        for (int nb = 0; nb < NB; nb++)
#pragma unroll
            for (int q = 0; q < 4; q++) acc[m][nb][q] = 0.0f;

#pragma unroll
    for (int tap = 0; tap < 9; tap++) {
        const int dy = tap / 3 - 1, dx = tap % 3 - 1;
        const float* ar0 = s_in + ((pyw + dy + 1) * 18 + dx + 1) * RS;
        const float* ar1 = ar0 + 18 * RS;
        const float* wt = s_w + tap * COUT * KP;
#pragma unroll
        for (int kb = 0; kb < CINP / 8; kb++) {
            const int k0 = kb * 8;
            unsigned a0[4], a1[4];
            a0[0] = __float_as_uint(ar0[g * RS + k0 + t]);
            a0[1] = __float_as_uint(ar0[(g + 8) * RS + k0 + t]);
            a0[2] = __float_as_uint(ar0[g * RS + k0 + t + 4]);
            a0[3] = __float_as_uint(ar0[(g + 8) * RS + k0 + t + 4]);
            a1[0] = __float_as_uint(ar1[g * RS + k0 + t]);
            a1[1] = __float_as_uint(ar1[(g + 8) * RS + k0 + t]);
            a1[2] = __float_as_uint(ar1[g * RS + k0 + t + 4]);
            a1[3] = __float_as_uint(ar1[(g + 8) * RS + k0 + t + 4]);
#pragma unroll
            for (int nb = 0; nb < NB; nb++) {
                unsigned b0 = __float_as_uint(wt[(nb * 8 + g) * KP + k0 + t]);
                unsigned b1 = __float_as_uint(wt[(nb * 8 + g) * KP + k0 + t + 4]);
                mma8(acc[0][nb], a0, b0, b1);
                mma8(acc[1][nb], a1, b0, b1);
            }
        }
    }

    // epilogue: bias (+resid) (+relu), NHWC float2 stores
#pragma unroll
    for (int m = 0; m < 2; m++) {
        int oy = by + pyw + m;
        long rowbase = (long)(n * H + oy) * W;
#pragma unroll
        for (int nb = 0; nb < NB; nb++) {
            int co = nb * 8 + 2 * t;
            float bv0 = bias[co], bv1 = bias[co + 1];
            long i0 = (rowbase + bx + g) * COUT + co;
            long i1 = (rowbase + bx + g + 8) * COUT + co;
            float2 v0 = make_float2(acc[m][nb][0] + bv0, acc[m][nb][1] + bv1);
            float2 v1 = make_float2(acc[m][nb][2] + bv0, acc[m][nb][3] + bv1);
            if (RESID) {
                float2 r0 = *(const float2*)(resid + i0);
                float2 r1 = *(const float2*)(resid + i1);
                v0.x += r0.x; v0.y += r0.y; v1.x += r1.x; v1.y += r1.y;
            }
            if (RELU_OUT) {
                v0.x = fmaxf(v0.x, 0.0f); v0.y = fmaxf(v0.y, 0.0f);
                v1.x = fmaxf(v1.x, 0.0f); v1.y = fmaxf(v1.y, 0.0f);
            }
            *(float2*)(out + i0) = v0;
            *(float2*)(out + i1) = v1;
        }
    }
}

// ---------------- maxpool 3x3 s2 p1, NHWC ----------------
__global__ void maxpool_nhwc(const float* __restrict__ in, float* __restrict__ out,
                             int C, int H, int W) {
    int H2 = H >> 1, W2 = W >> 1;
    long total = (long)512 * H2 * W2 * C;
    long i = (long)blockIdx.x * blockDim.x + threadIdx.x;
    if (i >= total) return;
    int c = (int)(i % C); long r = i / C;
    int ox = (int)(r % W2); r /= W2;
    int oy = (int)(r % H2); int n = (int)(r / H2);
    float m = -3.4e38f;
    int y0 = oy * 2 - 1, x0 = ox * 2 - 1;
#pragma unroll
    for (int dy = 0; dy < 3; dy++) {
        int y = y0 + dy;
        if (y < 0 || y >= H) continue;
#pragma unroll
        for (int dx = 0; dx < 3; dx++) {
            int x = x0 + dx;
            if (x < 0 || x >= W) continue;
            m = fmaxf(m, in[((long)(n * H + y) * W + x) * C + c]);
        }
    }
    out[i] = m;   // out index == ((n*H2+oy)*W2+ox)*C + c == i
}

// ---------------- CBAM channel attention (NHWC x: [n][256][32]) -----------
__global__ void cbam_ca_nhwc(const float* __restrict__ x, const float* __restrict__ fc1,
                             const float* __restrict__ fc2, float* __restrict__ ca) {
    int n = blockIdx.x, tid = threadIdx.x;
    int g = tid >> 5, c = tid & 31;
    __shared__ float rs[8][32], rm[8][32], s_mean[32], s_max[32], s_h[8];
    float sm = 0.0f, mx = -3.4e38f;
    for (int p = g; p < 256; p += 8) {
        float v = x[((long)n * 256 + p) * 32 + c];
        sm += v; mx = fmaxf(mx, v);
    }
    rs[g][c] = sm; rm[g][c] = mx;
    __syncthreads();
    if (tid < 32) {
        float s = 0.0f, m = -3.4e38f;
        for (int q = 0; q < 8; q++) { s += rs[q][tid]; m = fmaxf(m, rm[q][tid]); }
        s_mean[tid] = s * (1.0f / 256.0f); s_max[tid] = m;
    }
    __syncthreads();
    if (tid < 8) {
        float hm = 0.0f, hx = 0.0f;
        for (int k = 0; k < 32; k++) {
            float wv = fc1[tid * 32 + k];
            hm += s_mean[k] * wv; hx += s_max[k] * wv;
        }
        s_h[tid] = fmaxf(hm, 0.0f) + fmaxf(hx, 0.0f);
    }
    __syncthreads();
    if (tid < 32) {
        float o = 0.0f;
        for (int j = 0; j < 8; j++) o += s_h[j] * fc2[tid * 8 + j];
        ca[n * 32 + tid] = sigf(o);
    }
}

// apply channel attention in place; emit spatial mean/max maps
__global__ void cbam_apply_nhwc(float* x, const float* __restrict__ ca, float* __restrict__ sp) {
    int n = blockIdx.x, p = threadIdx.x;
    __shared__ float s_ca[32];
    if (p < 32) s_ca[p] = ca[n * 32 + p];
    __syncthreads();
    float* base = x + ((long)n * 256 + p) * 32;
    float sum = 0.0f, mx = -3.4e38f;
#pragma unroll
    for (int c = 0; c < 32; c++) {
        float v = base[c] * s_ca[c];
        base[c] = v;
        sum += v; mx = fmaxf(mx, v);
    }
    sp[(long)n * 512 + p] = sum * (1.0f / 32.0f);
    sp[(long)n * 512 + 256 + p] = mx;
}

// 7x7 spatial attention conv + apply (NHWC)
__global__ void cbam_sa_nhwc(float* x, const float* __restrict__ sp, const float* __restrict__ spw) {
    int n = blockIdx.x, p = threadIdx.x;
    int oy = p >> 4, ox = p & 15;
    __shared__ float s_sp[512], s_w[98];
    s_sp[p] = sp[(long)n * 512 + p];
    s_sp[256 + p] = sp[(long)n * 512 + 256 + p];
    if (p < 98) s_w[p] = spw[p];
    __syncthreads();
    float a = 0.0f;
#pragma unroll
    for (int ci = 0; ci < 2; ci++)
        for (int ky = 0; ky < 7; ky++) {
            int y = oy + ky - 3;
            if (y < 0 || y >= 16) continue;
            for (int kx = 0; kx < 7; kx++) {
                int xx = ox + kx - 3;
                if (xx < 0 || xx >= 16) continue;
                a = fmaf(s_sp[ci * 256 + y * 16 + xx], s_w[(ci * 7 + ky) * 7 + kx], a);
            }
        }
    float sa = sigf(a);
    float* base = x + ((long)n * 256 + p) * 32;
#pragma unroll
    for (int c = 0; c < 32; c++) base[c] *= sa;
}

// permute fc_w[n][c*256+p] -> g_fcwT[n][p*32+c] (matches NHWC flatten)
__global__ void fcw_permute(const float* __restrict__ w, float* __restrict__ wt) {
    int i = blockIdx.x * 256 + threadIdx.x;
    if (i >= 256 * 8192) return;
    int n = i >> 13;
    int r = i & 8191;
    int c = r >> 8, p = r & 255;
    wt[(n << 13) + p * 32 + c] = w[i];
}

// ---------------- GEMM: C[M,N] = A[M,K] @ B[N,K]^T + bias, opt relu ------
__global__ void gemm_bt_kernel(const float* __restrict__ A, const float* __restrict__ B,
                               const float* __restrict__ bias, float* __restrict__ C,
                               int M, int N, int K, int relu) {
    __shared__ float sA[32 * 33];
    __shared__ float sB[32 * 33];
    int bm = blockIdx.y * 32, bn = blockIdx.x * 32;
    int tid = threadIdx.x;
    int tr = tid >> 4, tc = tid & 15;
    float acc00 = 0, acc01 = 0, acc10 = 0, acc11 = 0;
    for (int k0 = 0; k0 < K; k0 += 32) {
        for (int i = tid; i < 32 * 32; i += 256) {
            int r = i >> 5, c = i & 31;
            sA[r * 33 + c] = (bm + r < M) ? A[(long)(bm + r) * K + k0 + c] : 0.0f;
            sB[r * 33 + c] = (bn + r < N) ? B[(long)(bn + r) * K + k0 + c] : 0.0f;
        }
        __syncthreads();
#pragma unroll
        for (int k = 0; k < 32; k++) {
            float a0 = sA[(tr * 2) * 33 + k], a1 = sA[(tr * 2 + 1) * 33 + k];
            float b0 = sB[(tc * 2) * 33 + k], b1 = sB[(tc * 2 + 1) * 33 + k];
            acc00 = fmaf(a0, b0, acc00); acc01 = fmaf(a0, b1, acc01);
            acc10 = fmaf(a1, b0, acc10); acc11 = fmaf(a1, b1, acc11);
        }
        __syncthreads();
    }
    float accs[2][2] = {{acc00, acc01}, {acc10, acc11}};
#pragma unroll
    for (int r = 0; r < 2; r++)
#pragma unroll
        for (int c = 0; c < 2; c++) {
            int m = bm + tr * 2 + r, nn = bn + tc * 2 + c;
            if (m < M && nn < N) {
                float v = accs[r][c] + bias[nn];
                if (relu) v = fmaxf(v, 0.0f);
                C[(long)m * N + nn] = v;
            }
        }
}

// ---------------- GRU scan: one block per env (8 blocks, 384 threads) ----
__global__ void gru_scan_kernel(const float* __restrict__ gi, const float* __restrict__ done,
                                const float* __restrict__ h0, const float* __restrict__ whh,
                                const float* __restrict__ bhh, float* __restrict__ hidden) {
    extern __shared__ float sm[];
    float* s_whh = sm;                 // transposed: [k*384 + j]
    float* s_gh = sm + 128 * 384;
    float* s_h = s_gh + 384;
    float* s_hm = s_h + 128;
    int b = blockIdx.x, j = threadIdx.x;

    for (int i = j; i < 384 * 128; i += 384) {
        int jj = i >> 7, k = i & 127;
        s_whh[k * 384 + jj] = whh[i];
    }
    if (j < 128) s_h[j] = h0[b * 128 + j];
    __syncthreads();

    float bh = bhh[j];
    for (int t = 0; t < 64; t++) {
        float dt = done[t * 8 + b];
        if (j < 128) s_hm[j] = (1.0f - dt) * s_h[j];
        __syncthreads();
        float acc = bh;
#pragma unroll 8
        for (int k = 0; k < 128; k++) acc = fmaf(s_hm[k], s_whh[k * 384 + j], acc);
        s_gh[j] = acc;
        __syncthreads();
        if (j < 128) {
            const float* gr = gi + (long)(t * 8 + b) * 384;
            float r = sigf(gr[j] + s_gh[j]);
            float z = sigf(gr[128 + j] + s_gh[128 + j]);
            float nn = tanhf(gr[256 + j] + r * s_gh[256 + j]);
            float hn = (1.0f - z) * nn + z * s_hm[j];
            s_h[j] = hn;
            hidden[(long)(t * 8 + b) * 128 + j] = hn;
        }
        __syncthreads();
    }
}

// ---------------- actor/critic heads ----------------
__global__ void heads_kernel(const float* __restrict__ hidden, const float* __restrict__ aw,
                             const float* __restrict__ ab, const float* __restrict__ cw,
                             const float* __restrict__ cb, float* __restrict__ out) {
    int row = blockIdx.x, t = threadIdx.x;
    __shared__ float s_h[128];
    s_h[t] = hidden[(long)row * 128 + t];
    __syncthreads();
    if (t < 4) {
        const float* w = (t < 3) ? (aw + t * 128) : cw;
        float s = (t < 3) ? ab[t] : cb[0];
        for (int k = 0; k < 128; k++) s = fmaf(s_h[k], w[k], s);
        out[row * 4 + t] = s;
    }
}

// ---------------- host-side launch helpers ----------------
template <int CIN, int COUT, bool RELU_IN, bool RESID, bool RELU_OUT, bool NCHW>
static void launch_conv(const float* in, const float* w, const float* b,
                        float* out, const float* resid, int H, int W) {
    constexpr int CINP = (CIN + 7) / 8 * 8;
    int smem = (324 * (CINP + 4) + 9 * COUT * (CINP + 4)) * 4;
    auto kfn = conv_mma_kernel<CIN, COUT, RELU_IN, RESID, RELU_OUT, NCHW>;
    cudaFuncSetAttribute(kfn, cudaFuncAttributeMaxDynamicSharedMemorySize, smem);
    dim3 grid(W / 16, H / 16, 512);
    kfn<<<grid, 256, smem>>>(in, w, b, out, resid, H, W);
}

static void launch_pool(const float* in, float* out, int C, int H, int W) {
    long total = (long)512 * C * (H / 2) * (W / 2);
    maxpool_nhwc<<<(unsigned)((total + 255) / 256), 256>>>(in, out, C, H, W);
}

extern "C" void kernel_launch(void* const* d_in, const int* in_sizes, int n_in,
                              void* d_out, int out_size) {
    (void)in_sizes; (void)n_in; (void)out_size;
    const float* x        = (const float*)d_in[0];
    const float* done     = (const float*)d_in[1];
    const float* grustate = (const float*)d_in[2];
    const float* s0_cw = (const float*)d_in[3];
    const float* s0_cb = (const float*)d_in[4];
    const float* s0_rw = (const float*)d_in[5];
    const float* s0_rb = (const float*)d_in[6];
    const float* s1_cw = (const float*)d_in[7];
    const float* s1_cb = (const float*)d_in[8];
    const float* s1_rw = (const float*)d_in[9];
    const float* s1_rb = (const float*)d_in[10];
    const float* s2_cw = (const float*)d_in[11];
    const float* s2_cb = (const float*)d_in[12];
    const float* s2_rw = (const float*)d_in[13];
    const float* s2_rb = (const float*)d_in[14];
    const float* cbam_fc1 = (const float*)d_in[15];
    const float* cbam_fc2 = (const float*)d_in[16];
    const float* cbam_spw = (const float*)d_in[17];
    const float* fc_w  = (const float*)d_in[18];
    const float* fc_b  = (const float*)d_in[19];
    const float* gwih  = (const float*)d_in[20];
    const float* gwhh  = (const float*)d_in[21];
    const float* gbih  = (const float*)d_in[22];
    const float* gbhh  = (const float*)d_in[23];
    const float* aw    = (const float*)d_in[24];
    const float* ab    = (const float*)d_in[25];
    const float* cw    = (const float*)d_in[26];
    const float* cb    = (const float*)d_in[27];
    float* out = (float*)d_out;

    float *P, *X, *O, *CA, *SP, *FEAT, *GI, *HID, *FCWT;
    cudaGetSymbolAddress((void**)&P, g_P);
    cudaGetSymbolAddress((void**)&X, g_X);
    cudaGetSymbolAddress((void**)&O, g_O);
    cudaGetSymbolAddress((void**)&CA, g_ca);
    cudaGetSymbolAddress((void**)&SP, g_sp);
    cudaGetSymbolAddress((void**)&FEAT, g_feat);
    cudaGetSymbolAddress((void**)&GI, g_gi);
    cudaGetSymbolAddress((void**)&HID, g_hid);
    cudaGetSymbolAddress((void**)&FCWT, g_fcwT);

    // fc_w permutation for NHWC flatten (independent; launch early)
    fcw_permute<<<(256 * 8192 + 255) / 256, 256>>>(fc_w, FCWT);

    // ---- stage 0: 6->16 @128 (NCHW src) -> pool 64 -> 2 resblocks ----
    launch_conv<6, 16, false, false, false, true>(x, s0_cw, s0_cb, P, nullptr, 128, 128);
    launch_pool(P, X, 16, 128, 128);
    launch_conv<16, 16, true, false, false, false>(X, s0_rw + 0 * 2304, s0_rb + 0,  O, nullptr, 64, 64);
    launch_conv<16, 16, true, true,  false, false>(O, s0_rw + 1 * 2304, s0_rb + 16, X, X, 64, 64);
    launch_conv<16, 16, true, false, false, false>(X, s0_rw + 2 * 2304, s0_rb + 32, O, nullptr, 64, 64);
    launch_conv<16, 16, true, true,  false, false>(O, s0_rw + 3 * 2304, s0_rb + 48, X, X, 64, 64);

    // ---- stage 1: 16->32 @64 -> pool 32 -> 2 resblocks ----
    launch_conv<16, 32, false, false, false, false>(X, s1_cw, s1_cb, P, nullptr, 64, 64);
    launch_pool(P, X, 32, 64, 64);
    launch_conv<32, 32, true, false, false, false>(X, s1_rw + 0 * 9216, s1_rb + 0,  O, nullptr, 32, 32);
    launch_conv<32, 32, true, true,  false, false>(O, s1_rw + 1 * 9216, s1_rb + 32, X, X, 32, 32);
    launch_conv<32, 32, true, false, false, false>(X, s1_rw + 2 * 9216, s1_rb + 64, O, nullptr, 32, 32);
    launch_conv<32, 32, true, true,  false, false>(O, s1_rw + 3 * 9216, s1_rb + 96, X, X, 32, 32);

    // ---- stage 2: 32->32 @32 -> pool 16 -> 2 resblocks (last fuses final relu) ----
    launch_conv<32, 32, false, false, false, false>(X, s2_cw, s2_cb, P, nullptr, 32, 32);
    launch_pool(P, X, 32, 32, 32);
    launch_conv<32, 32, true, false, false, false>(X, s2_rw + 0 * 9216, s2_rb + 0,  O, nullptr, 16, 16);
    launch_conv<32, 32, true, true,  false, false>(O, s2_rw + 1 * 9216, s2_rb + 32, X, X, 16, 16);
    launch_conv<32, 32, true, false, false, false>(X, s2_rw + 2 * 9216, s2_rb + 64, O, nullptr, 16, 16);
    launch_conv<32, 32, true, true,  true,  false>(O, s2_rw + 3 * 9216, s2_rb + 96, X, X, 16, 16);

    // ---- CBAM (NHWC) ----
    cbam_ca_nhwc<<<512, 256>>>(X, cbam_fc1, cbam_fc2, CA);
    cbam_apply_nhwc<<<512, 256>>>(X, CA, SP);
    cbam_sa_nhwc<<<512, 256>>>(X, SP, cbam_spw);

    // ---- FC 8192->256 (+relu), NHWC-k permuted weights ----
    gemm_bt_kernel<<<dim3(256 / 32, 512 / 32), 256>>>(X, FCWT, fc_b, FEAT, 512, 256, 8192, 1);

    // ---- GRU: input gates GEMM, then sequential scan ----
    gemm_bt_kernel<<<dim3(384 / 32, 512 / 32), 256>>>(FEAT, gwih, gbih, GI, 512, 384, 256, 0);
    {
        int smem = (128 * 384 + 384 + 128 + 128) * 4;
        cudaFuncSetAttribute(gru_scan_kernel, cudaFuncAttributeMaxDynamicSharedMemorySize, smem);
        gru_scan_kernel<<<8, 384, smem>>>(GI, done, grustate, gwhh, gbhh, HID);
    }

    // ---- actor / critic heads -> (512, 4) ----
    heads_kernel<<<512, 128>>>(HID, aw, ab, cw, cb, out);
}